// round 15
// baseline (speedup 1.0000x reference)
#include <cuda_runtime.h>
#include <cuda_fp16.h>
#include <math.h>

#define NN 100000
#define NE 1600000
#define NPAD (NE + 8 * NN)
#define HID 64
#define INC 128
#define OUTC 40
#define NLAYERS 8
#define GRID_P 444             // prep: 148 x 3 @256thr
#define GRID_L 444             // layers: 148 x 3 @256thr, guaranteed resident
#define GRID_E 592
#define BLK 256
#define NTILES 98              // ceil(NN/1024)

typedef unsigned long long u64;

__device__ __forceinline__ u64 pack2(float a, float b) {
    u64 r; asm("mov.b64 %0, {%1, %2};" : "=l"(r) : "f"(a), "f"(b)); return r;
}
__device__ __forceinline__ void unpack2(float& a, float& b, u64 v) {
    asm("mov.b64 {%0, %1}, %2;" : "=f"(a), "=f"(b) : "l"(v));
}
__device__ __forceinline__ u64 ffma2(u64 a, u64 b, u64 c) {
    u64 d; asm("fma.rn.f32x2 %0, %1, %2, %3;" : "=l"(d) : "l"(a), "l"(b), "l"(c)); return d;
}

// ---------------- scratch ----------------------------------------------------
__device__ float g_h[NN * HID];
__device__ uint2 g_hh[(NN + 1) * 16];  // fp16 dinv[r]*h[r]; row NN = zero sentinel
__device__ float4 g_h0[NN * 16];       // 4-ch layout: [node][cg] = ch 4cg..4cg+3
__device__ float g_s2[NN * HID];
__device__ float g_dinv[NN];
__device__ int   g_degi[NN];
__device__ __align__(16) int g_off[NN + 8];
__device__ int   g_cursor[NN];
__device__ __align__(16) int g_edge[NPAD];  // row index only; pad = NN (sentinel)
__device__ float g_bnS[2][HID];
__device__ float g_bnQ[2][HID];
__device__ u64   g_tdesc[128];
__device__ int   g_tctr;
__device__ int   g_psync;
__device__ int   g_lctr;
__device__ int   g_is64;

__device__ __forceinline__ int load_idx(const void* ei, int which, int e) {
    if (g_is64) return (int)((const long long*)ei)[(long long)which * NE + e];
    return ((const int*)ei)[which * NE + e];
}

// grid-wide sync. Arrival: one atomic. Wait: RELAXED LOADS (no atomic-ALU
// serialization) + nanosleep backoff. Fences carry release/acquire + L1 flush.
__device__ __forceinline__ void gsync(int* ctr, int target) {
    __threadfence();
    __syncthreads();
    if (threadIdx.x == 0) {
        atomicAdd(ctr, 1);
        int v;
        for (;;) {
            asm volatile("ld.relaxed.gpu.global.s32 %0, [%1];"
                         : "=r"(v) : "l"(ctr) : "memory");
            if (v >= target) break;
            __nanosleep(128);
        }
    }
    __syncthreads();
    __threadfence();
}

// ---- launch 0: reset grid-sync counters (must precede k_prep) ---------------
__global__ void k_init() {
    if (threadIdx.x == 0) g_psync = 0;
    if (threadIdx.x == 1) g_lctr = 0;
}

// ---- launch 1: persistent preprocessing (init -> deg -> scan -> fill) -------
__global__ void __launch_bounds__(256, 3) k_prep(const void* ei) {
    int tid = blockIdx.x * blockDim.x + threadIdx.x;
    int nthr = gridDim.x * blockDim.x;
    for (int i = tid; i < NN; i += nthr) { g_degi[i] = 1; g_cursor[i] = 0; }
    if (blockIdx.x == 0) {
        int t = threadIdx.x;
        if (t < 128) g_tdesc[t] = 0ULL;
        if (t == 128) g_tctr = 0;
        if (t < 32) {
            const int* ei32 = (const int*)ei;
            int nz = 0;
            for (int j = t; j < 256; j += 32) nz |= ei32[2 * j + 1];
            unsigned any = __ballot_sync(0xffffffffu, nz != 0);
            if (t == 0) g_is64 = (any == 0) ? 1 : 0;
        }
    }
    gsync(&g_psync, GRID_P);
    // phase 1: full sentinel fill (coalesced STG.128 stream) + degree histogram
    for (int i = tid; i < NPAD / 4; i += nthr)
        ((int4*)g_edge)[i] = make_int4(NN, NN, NN, NN);
    for (int e = tid; e < NE; e += nthr) {
        int c = load_idx(ei, 1, e);
        if (c >= 0 && c < NN) atomicAdd(&g_degi[c], 1);
    }
    gsync(&g_psync, 2 * GRID_P);
    // phase 2: decoupled-lookback scan of padded degrees
    {
        __shared__ int s_tile, s_pfx, sm[256];
        if (threadIdx.x == 0) s_tile = atomicAdd(&g_tctr, 1);
        __syncthreads();
        int tile = s_tile;
        if (tile < NTILES) {
            int base = tile * 1024 + threadIdx.x * 4;
            int v0 = (base + 0 < NN) ? ((g_degi[base + 0] + 7) & ~7) : 0;
            int v1 = (base + 1 < NN) ? ((g_degi[base + 1] + 7) & ~7) : 0;
            int v2 = (base + 2 < NN) ? ((g_degi[base + 2] + 7) & ~7) : 0;
            int v3 = (base + 3 < NN) ? ((g_degi[base + 3] + 7) & ~7) : 0;
            int tsum = v0 + v1 + v2 + v3;
            sm[threadIdx.x] = tsum;
            __syncthreads();
            for (int d = 1; d < 256; d <<= 1) {
                int t = (threadIdx.x >= d) ? sm[threadIdx.x - d] : 0;
                __syncthreads();
                if (threadIdx.x >= d) sm[threadIdx.x] += t;
                __syncthreads();
            }
            if (threadIdx.x == 0) {
                int total = sm[255];
                if (tile == 0) {
                    atomicExch(&g_tdesc[0], (2ULL << 32) | (unsigned)total);
                    s_pfx = 0;
                } else {
                    atomicExch(&g_tdesc[tile], (1ULL << 32) | (unsigned)total);
                    int pfx = 0;
                    for (int t = tile - 1; t >= 0; t--) {
                        u64 d;
                        for (;;) {
                            asm volatile("ld.relaxed.gpu.global.u64 %0, [%1];"
                                         : "=l"(d) : "l"(&g_tdesc[t]) : "memory");
                            if ((d >> 32) != 0) break;
                        }
                        pfx += (int)(d & 0xffffffffULL);
                        if ((d >> 32) == 2) break;
                    }
                    atomicExch(&g_tdesc[tile], (2ULL << 32) | (unsigned)(pfx + total));
                    s_pfx = pfx;
                }
            }
            __syncthreads();
            int run = s_pfx + sm[threadIdx.x] - tsum;
            if (base + 0 < NN) g_off[base + 1] = run + v0;
            if (base + 1 < NN) g_off[base + 2] = run + v0 + v1;
            if (base + 2 < NN) g_off[base + 3] = run + v0 + v1 + v2;
            if (base + 3 < NN) g_off[base + 4] = run + v0 + v1 + v2 + v3;
            if (tile == 0 && threadIdx.x == 0) g_off[0] = 0;
        }
    }
    gsync(&g_psync, 3 * GRID_P);
    // phase 3: dinv + CSC edge fill (+ self loops)
    for (int i = tid; i < NN; i += nthr)
        g_dinv[i] = rsqrtf((float)g_degi[i]);
    for (int i = tid; i < NE + NN; i += nthr) {
        if (i < NE) {
            int r = load_idx(ei, 0, i);
            int c = load_idx(ei, 1, i);
            if (r < 0) r = 0; if (r >= NN) r = NN - 1;
            if (c < 0) c = 0; if (c >= NN) c = NN - 1;
            int p = g_off[c] + atomicAdd(&g_cursor[c], 1);
            g_edge[p] = r;
        } else {
            int c = i - NE;
            int p = g_off[c] + atomicAdd(&g_cursor[c], 1);
            g_edge[p] = c;
        }
    }
}

// ---- launch 2: input GEMM; writes hh2 = dinv*relu(xW0+b0), h0, sentinel -----
__global__ void __launch_bounds__(256, 4) k_in(const float* __restrict__ x,
                                               const float* __restrict__ W0,
                                               const float* __restrict__ b0) {
    if (blockIdx.x == 0) {
        int t = threadIdx.x;
        if (t < HID) { g_bnS[0][t] = 0.f; g_bnQ[0][t] = 0.f; }
        if (t >= HID && t < HID + 16) g_hh[NN * 16 + (t - HID)] = make_uint2(0, 0);
    }
    __shared__ float2 Ws[INC][32];
    for (int idx = threadIdx.x; idx < INC * 32; idx += blockDim.x) {
        int k = idx >> 5, j = idx & 31;
        Ws[k][j] = make_float2(W0[k * HID + 2 * j], W0[k * HID + 2 * j + 1]);
    }
    __syncthreads();
    const u64* __restrict__ Wsu = reinterpret_cast<const u64*>(&Ws[0][0]);
    int lane = threadIdx.x & 31;
    int cg = lane & 15;
    int gw = (blockIdx.x * blockDim.x + threadIdx.x) >> 5;
    int nw = (gridDim.x * blockDim.x) >> 5;
    float2 bv = ((const float2*)b0)[lane];
    for (int base = gw * 4; base < NN; base += nw * 4) {
        float4 xv[4];
#pragma unroll
        for (int u = 0; u < 4; u++)
            xv[u] = ((const float4*)x)[(base + u) * 32 + lane];
        u64 acc[4] = {0, 0, 0, 0};
#pragma unroll 4
        for (int k = 0; k < INC; k++) {
            u64 wv = Wsu[k * 32 + lane];
            int src = k >> 2;
#pragma unroll
            for (int u = 0; u < 4; u++) {
                float comp = ((k & 3) == 0) ? xv[u].x : ((k & 3) == 1) ? xv[u].y
                           : ((k & 3) == 2) ? xv[u].z : xv[u].w;
                float xk = __shfl_sync(0xffffffffu, comp, src);
                acc[u] = ffma2(pack2(xk, xk), wv, acc[u]);
            }
        }
#pragma unroll
        for (int u = 0; u < 4; u++) {
            float ox, oy;
            unpack2(ox, oy, acc[u]);
            ox = fmaxf(ox + bv.x, 0.f);
            oy = fmaxf(oy + bv.y, 0.f);
            float dc = g_dinv[base + u];
            ((__half2*)g_hh)[(base + u) * 32 + lane] =
                __floats2half2_rn(dc * ox, dc * oy);
            float lx0 = __shfl_sync(0xffffffffu, ox, 2 * cg);
            float ly0 = __shfl_sync(0xffffffffu, oy, 2 * cg);
            float lx1 = __shfl_sync(0xffffffffu, ox, 2 * cg + 1);
            float ly1 = __shfl_sync(0xffffffffu, oy, 2 * cg + 1);
            if (lane < 16)
                g_h0[(base + u) * 16 + lane] = make_float4(lx0, ly0, lx1, ly1);
        }
    }
}

// ---- launch 3: ALL 8 layers, persistent, grid-synced ------------------------
// U=8 node batches; bare-index edges; all 9 offsets prefetched per batch.
__global__ void __launch_bounds__(BLK, 3) k_layers(const float* __restrict__ convW,
                                                   const float* __restrict__ gam,
                                                   const float* __restrict__ bet) {
    __shared__ float2 Ws[HID][32];                 // 16 KB
    __shared__ __align__(16) float4 stg[8][8][16]; // 16 KB: per-warp s staging
    __shared__ float2 rS[8][32], rQ[8][32];
    __shared__ float s_scale[HID], s_shift[HID];
    int lane = threadIdx.x & 31;
    int wid = threadIdx.x >> 5;
    int hl = lane >> 4;
    int cg = lane & 15;
    int gw = (blockIdx.x * blockDim.x + threadIdx.x) >> 5;
    int nw = (gridDim.x * blockDim.x) >> 5;
    const uint2* __restrict__ hhp = g_hh;
    const float4* __restrict__ h0p = g_h0;
    float2* __restrict__ s2p = (float2*)g_s2;
    int step = 0;

    for (int l = 0; l < NLAYERS; l++) {
        int par = l & 1;
        float beta_l = logf(0.5f / (float)(l + 1) + 1.0f);
        float ob = 1.0f - beta_l;
        const float* Wc = convW + l * HID * HID;
        for (int idx = threadIdx.x; idx < HID * 32; idx += blockDim.x) {
            int k = idx >> 5, j = idx & 31;
            Ws[k][j] = make_float2(Wc[k * HID + 2 * j], Wc[k * HID + 2 * j + 1]);
        }
        __syncthreads();
        const u64* __restrict__ Wsu = reinterpret_cast<const u64*>(&Ws[0][0]);
        float2 bsum = {0, 0}, bsq = {0, 0};

        for (int base = gw * 8; base < NN; base += nw * 8) {
            // prefetch all 9 offsets: kills the per-node off->meta serial chain
            int4 oa = *(const int4*)&g_off[base];
            int4 ob4 = *(const int4*)&g_off[base + 4];
            int o8 = g_off[base + 8];
            int offv[9] = {oa.x, oa.y, oa.z, oa.w,
                           ob4.x, ob4.y, ob4.z, ob4.w, o8};
            // ---- gather + residual for 8 nodes; stage s rows in smem ----
#pragma unroll
            for (int u = 0; u < 8; u++) {
                int node = base + u;
                int e0 = offv[u], e1 = offv[u + 1];
                float ax = 0.f, ay = 0.f, az = 0.f, aw = 0.f;
#define GATH(i0, i1) { \
    int r_ = hl ? (i1) : (i0); \
    uint2 v_ = __ldg(&hhp[r_ * 16 + cg]); \
    float2 f0_ = __half22float2(*(const __half2*)&v_.x); \
    float2 f1_ = __half22float2(*(const __half2*)&v_.y); \
    ax += f0_.x; ay += f0_.y; az += f1_.x; aw += f1_.y; }
                for (int e = e0; e < e1; e += 8) {
                    const int4* ip = (const int4*)(g_edge + e);
                    int4 a = ip[0], b = ip[1];
                    GATH(a.x, a.y) GATH(a.z, a.w)
                    GATH(b.x, b.y) GATH(b.z, b.w)
                }
#undef GATH
                ax += __shfl_xor_sync(0xffffffffu, ax, 16);
                ay += __shfl_xor_sync(0xffffffffu, ay, 16);
                az += __shfl_xor_sync(0xffffffffu, az, 16);
                aw += __shfl_xor_sync(0xffffffffu, aw, 16);
                float c9 = 0.9f * g_dinv[node];
                float4 h0v = h0p[node * 16 + cg];
                float4 sv;
                sv.x = fmaf(c9, ax, 0.1f * h0v.x);
                sv.y = fmaf(c9, ay, 0.1f * h0v.y);
                sv.z = fmaf(c9, az, 0.1f * h0v.z);
                sv.w = fmaf(c9, aw, 0.1f * h0v.w);
                if (hl == 0) stg[wid][u][cg] = sv;
            }
            __syncwarp();
            // ---- GEMM from smem staging: t[u] (2 ch/lane) = s[u] @ W ----
            u64 t[8] = {0, 0, 0, 0, 0, 0, 0, 0};
#pragma unroll 4
            for (int q = 0; q < 16; q++) {
                u64 w0 = Wsu[(4 * q + 0) * 32 + lane];
                u64 w1 = Wsu[(4 * q + 1) * 32 + lane];
                u64 w2 = Wsu[(4 * q + 2) * 32 + lane];
                u64 w3 = Wsu[(4 * q + 3) * 32 + lane];
#pragma unroll
                for (int u = 0; u < 8; u++) {
                    float4 sq = stg[wid][u][q];      // broadcast LDS.128
                    t[u] = ffma2(pack2(sq.x, sq.x), w0, t[u]);
                    t[u] = ffma2(pack2(sq.y, sq.y), w1, t[u]);
                    t[u] = ffma2(pack2(sq.z, sq.z), w2, t[u]);
                    t[u] = ffma2(pack2(sq.w, sq.w), w3, t[u]);
                }
            }
#pragma unroll
            for (int u = 0; u < 8; u++) {
                int node = base + u;
                float2 sl = *(const float2*)((const float*)&stg[wid][u][0] + 2 * lane);
                float tx, ty;
                unpack2(tx, ty, t[u]);
                float2 o;
                o.x = ob * sl.x + beta_l * tx;
                o.y = ob * sl.y + beta_l * ty;
                s2p[node * 32 + lane] = o;
                bsum.x += o.x; bsum.y += o.y;
                bsq.x = fmaf(o.x, o.x, bsq.x);
                bsq.y = fmaf(o.y, o.y, bsq.y);
            }
            __syncwarp();
        }

        __syncthreads();
        rS[wid][lane] = bsum; rQ[wid][lane] = bsq;
        __syncthreads();
        if (threadIdx.x < 32) {
            float2 S = rS[0][threadIdx.x], Q = rQ[0][threadIdx.x];
#pragma unroll
            for (int j = 1; j < 8; j++) {
                S.x += rS[j][threadIdx.x].x; S.y += rS[j][threadIdx.x].y;
                Q.x += rQ[j][threadIdx.x].x; Q.y += rQ[j][threadIdx.x].y;
            }
            atomicAdd(&g_bnS[par][2 * threadIdx.x],     S.x);
            atomicAdd(&g_bnS[par][2 * threadIdx.x + 1], S.y);
            atomicAdd(&g_bnQ[par][2 * threadIdx.x],     Q.x);
            atomicAdd(&g_bnQ[par][2 * threadIdx.x + 1], Q.y);
        }
        gsync(&g_lctr, (++step) * GRID_L);

        if (threadIdx.x < HID) {
            float inv = 1.0f / (float)NN;
            float mu = g_bnS[par][threadIdx.x] * inv;
            float var = g_bnQ[par][threadIdx.x] * inv - mu * mu;
            float rs = rsqrtf(var + 1e-5f);
            float sc = rs * gam[l * HID + threadIdx.x];
            s_scale[threadIdx.x] = sc;
            s_shift[threadIdx.x] = bet[l * HID + threadIdx.x] - mu * sc;
        } else if (threadIdx.x < 2 * HID) {
            g_bnS[par ^ 1][threadIdx.x - HID] = 0.f;
            g_bnQ[par ^ 1][threadIdx.x - HID] = 0.f;
        }
        __syncthreads();
        int writeF32 = (l == NLAYERS - 1);
        for (int i = blockIdx.x * blockDim.x + threadIdx.x; i < NN * 16;
             i += gridDim.x * blockDim.x) {
            float4 v = ((const float4*)g_s2)[i];
            int c = (i & 15) << 2;
            v.x = fmaxf(fmaf(v.x, s_scale[c],     s_shift[c]),     0.f);
            v.y = fmaxf(fmaf(v.y, s_scale[c + 1], s_shift[c + 1]), 0.f);
            v.z = fmaxf(fmaf(v.z, s_scale[c + 2], s_shift[c + 2]), 0.f);
            v.w = fmaxf(fmaf(v.w, s_scale[c + 3], s_shift[c + 3]), 0.f);
            float dc = g_dinv[i >> 4];
            __half2 p0 = __floats2half2_rn(dc * v.x, dc * v.y);
            __half2 p1 = __floats2half2_rn(dc * v.z, dc * v.w);
            uint2 pk;
            pk.x = *reinterpret_cast<unsigned int*>(&p0);
            pk.y = *reinterpret_cast<unsigned int*>(&p1);
            g_hh[i] = pk;
            if (writeF32) ((float4*)g_h)[i] = v;
        }
        gsync(&g_lctr, (++step) * GRID_L);
    }
}

// ---- launch 4: output GEMM out = h @ Wout + bout ----------------------------
__global__ void __launch_bounds__(256, 4) k_out(const float* __restrict__ Wout,
                                                const float* __restrict__ bout,
                                                float* __restrict__ out) {
    __shared__ float2 Wo[HID][32];
    for (int idx = threadIdx.x; idx < HID * 32; idx += blockDim.x) {
        int k = idx >> 5, j = idx & 31;
        float w0 = Wout[k * OUTC + j];
        float w1 = (j < 8) ? Wout[k * OUTC + 32 + j] : 0.f;
        Wo[k][j] = make_float2(w0, w1);
    }
    __syncthreads();
    const u64* __restrict__ Wou = reinterpret_cast<const u64*>(&Wo[0][0]);
    int lane = threadIdx.x & 31;
    int gw = (blockIdx.x * blockDim.x + threadIdx.x) >> 5;
    int nw = (gridDim.x * blockDim.x) >> 5;
    const float2* __restrict__ hp = (const float2*)g_h;
    float b0v = bout[lane];
    float b1v = (lane < 8) ? bout[32 + lane] : 0.f;
    for (int base = gw * 4; base < NN; base += nw * 4) {
        float2 hv[4];
#pragma unroll
        for (int u = 0; u < 4; u++) hv[u] = hp[(base + u) * 32 + lane];
        u64 acc[4] = {0, 0, 0, 0};
#pragma unroll 8
        for (int k = 0; k < HID; k++) {
            u64 wv = Wou[k * 32 + lane];
            int src = k >> 1;
#pragma unroll
            for (int u = 0; u < 4; u++) {
                float hk = __shfl_sync(0xffffffffu, (k & 1) ? hv[u].y : hv[u].x, src);
                acc[u] = ffma2(pack2(hk, hk), wv, acc[u]);
            }
        }
#pragma unroll
        for (int u = 0; u < 4; u++) {
            int node = base + u;
            float a0, a1;
            unpack2(a0, a1, acc[u]);
            out[node * OUTC + lane] = a0 + b0v;
            if (lane < 8) out[node * OUTC + 32 + lane] = a1 + b1v;
        }
    }
}

// ---- launcher ---------------------------------------------------------------
extern "C" void kernel_launch(void* const* d_in, const int* in_sizes, int n_in,
                              void* d_out, int out_size) {
    const float* x     = (const float*)d_in[0];
    const void*  ei    = d_in[1];
    const float* W0    = (const float*)d_in[2];
    const float* b0    = (const float*)d_in[3];
    const float* convW = (const float*)d_in[4];
    const float* gam   = (const float*)d_in[5];
    const float* bet   = (const float*)d_in[6];
    const float* Wout  = (const float*)d_in[7];
    const float* bout  = (const float*)d_in[8];
    float* out = (float*)d_out;

    k_init<<<1, 64>>>();                        // 0
    k_prep<<<GRID_P, 256>>>(ei);                // 1
    k_in<<<GRID_E, 256>>>(x, W0, b0);           // 2
    k_layers<<<GRID_L, BLK>>>(convW, gam, bet); // 3  <- profiled slot
    k_out<<<GRID_E, 256>>>(Wout, bout, out);    // 4
}

// round 16
// speedup vs baseline: 1.0912x; 1.0912x over previous
#include <cuda_runtime.h>
#include <cuda_fp16.h>
#include <math.h>

#define NN 100000
#define NE 1600000
#define NPAD (NE + 8 * NN)
#define HID 64
#define INC 128
#define OUTC 40
#define NLAYERS 8
#define GRID_P 444             // prep: 148 x 3 @256thr
#define GRID_L 444             // layers: 148 x 3 @256thr, guaranteed resident
#define GRID_E 592
#define BLK 256
#define NTILES 98              // ceil(NN/1024)

typedef unsigned long long u64;

__device__ __forceinline__ u64 pack2(float a, float b) {
    u64 r; asm("mov.b64 %0, {%1, %2};" : "=l"(r) : "f"(a), "f"(b)); return r;
}
__device__ __forceinline__ void unpack2(float& a, float& b, u64 v) {
    asm("mov.b64 {%0, %1}, %2;" : "=f"(a), "=f"(b) : "l"(v));
}
__device__ __forceinline__ u64 ffma2(u64 a, u64 b, u64 c) {
    u64 d; asm("fma.rn.f32x2 %0, %1, %2, %3;" : "=l"(d) : "l"(a), "l"(b), "l"(c)); return d;
}

// ---------------- scratch ----------------------------------------------------
__device__ float g_h[NN * HID];
__device__ uint2 g_hh[(NN + 1) * 16];  // fp16 dinv[r]*h[r]; row NN = zero sentinel
__device__ float4 g_h0[NN * 16];       // 4-ch layout: [node][cg] = ch 4cg..4cg+3
__device__ float g_s2[NN * HID];
__device__ float g_dinv[NN];
__device__ int   g_degi[NN];
__device__ __align__(16) int g_off[NN + 8];
__device__ int   g_cursor[NN];
__device__ __align__(16) int g_edge[NPAD];  // row index only; pad = NN (sentinel)
__device__ float g_bnS[2][HID];
__device__ float g_bnQ[2][HID];
__device__ u64   g_tdesc[128];
__device__ int   g_tctr;
__device__ int   g_psync;
__device__ int   g_lctr;
__device__ int   g_is64;

__device__ __forceinline__ int load_idx(const void* ei, int which, int e) {
    if (g_is64) return (int)((const long long*)ei)[(long long)which * NE + e];
    return ((const int*)ei)[which * NE + e];
}

// grid-wide sync (R13 form — atomic arrival + atomic poll; measured best)
__device__ __forceinline__ void gsync(int* ctr, int target) {
    __threadfence();
    __syncthreads();
    if (threadIdx.x == 0) {
        atomicAdd(ctr, 1);
        while (atomicAdd(ctr, 0) < target) { }
    }
    __syncthreads();
    __threadfence();
}

// ---- launch 0: reset grid-sync counters (must precede k_prep) ---------------
__global__ void k_init() {
    if (threadIdx.x == 0) g_psync = 0;
    if (threadIdx.x == 1) g_lctr = 0;
}

// ---- launch 1: persistent preprocessing (init -> deg -> scan -> fill) -------
__global__ void __launch_bounds__(256, 3) k_prep(const void* ei) {
    int tid = blockIdx.x * blockDim.x + threadIdx.x;
    int nthr = gridDim.x * blockDim.x;
    for (int i = tid; i < NN; i += nthr) { g_degi[i] = 1; g_cursor[i] = 0; }
    if (blockIdx.x == 0) {
        int t = threadIdx.x;
        if (t < 128) g_tdesc[t] = 0ULL;
        if (t == 128) g_tctr = 0;
        if (t < 32) {
            const int* ei32 = (const int*)ei;
            int nz = 0;
            for (int j = t; j < 256; j += 32) nz |= ei32[2 * j + 1];
            unsigned any = __ballot_sync(0xffffffffu, nz != 0);
            if (t == 0) g_is64 = (any == 0) ? 1 : 0;
        }
    }
    gsync(&g_psync, GRID_P);
    // phase 1: full sentinel fill (coalesced STG.128 stream) + degree histogram
    for (int i = tid; i < NPAD / 4; i += nthr)
        ((int4*)g_edge)[i] = make_int4(NN, NN, NN, NN);
    for (int e = tid; e < NE; e += nthr) {
        int c = load_idx(ei, 1, e);
        if (c >= 0 && c < NN) atomicAdd(&g_degi[c], 1);
    }
    gsync(&g_psync, 2 * GRID_P);
    // phase 2: decoupled-lookback scan of padded degrees
    {
        __shared__ int s_tile, s_pfx, sm[256];
        if (threadIdx.x == 0) s_tile = atomicAdd(&g_tctr, 1);
        __syncthreads();
        int tile = s_tile;
        if (tile < NTILES) {
            int base = tile * 1024 + threadIdx.x * 4;
            int v0 = (base + 0 < NN) ? ((g_degi[base + 0] + 7) & ~7) : 0;
            int v1 = (base + 1 < NN) ? ((g_degi[base + 1] + 7) & ~7) : 0;
            int v2 = (base + 2 < NN) ? ((g_degi[base + 2] + 7) & ~7) : 0;
            int v3 = (base + 3 < NN) ? ((g_degi[base + 3] + 7) & ~7) : 0;
            int tsum = v0 + v1 + v2 + v3;
            sm[threadIdx.x] = tsum;
            __syncthreads();
            for (int d = 1; d < 256; d <<= 1) {
                int t = (threadIdx.x >= d) ? sm[threadIdx.x - d] : 0;
                __syncthreads();
                if (threadIdx.x >= d) sm[threadIdx.x] += t;
                __syncthreads();
            }
            if (threadIdx.x == 0) {
                int total = sm[255];
                if (tile == 0) {
                    atomicExch(&g_tdesc[0], (2ULL << 32) | (unsigned)total);
                    s_pfx = 0;
                } else {
                    atomicExch(&g_tdesc[tile], (1ULL << 32) | (unsigned)total);
                    int pfx = 0;
                    for (int t = tile - 1; t >= 0; t--) {
                        u64 d;
                        do { d = atomicAdd(&g_tdesc[t], 0ULL); } while ((d >> 32) == 0);
                        pfx += (int)(d & 0xffffffffULL);
                        if ((d >> 32) == 2) break;
                    }
                    atomicExch(&g_tdesc[tile], (2ULL << 32) | (unsigned)(pfx + total));
                    s_pfx = pfx;
                }
            }
            __syncthreads();
            int run = s_pfx + sm[threadIdx.x] - tsum;
            if (base + 0 < NN) g_off[base + 1] = run + v0;
            if (base + 1 < NN) g_off[base + 2] = run + v0 + v1;
            if (base + 2 < NN) g_off[base + 3] = run + v0 + v1 + v2;
            if (base + 3 < NN) g_off[base + 4] = run + v0 + v1 + v2 + v3;
            if (tile == 0 && threadIdx.x == 0) g_off[0] = 0;
        }
    }
    gsync(&g_psync, 3 * GRID_P);
    // phase 3: dinv + CSC edge fill (+ self loops)
    for (int i = tid; i < NN; i += nthr)
        g_dinv[i] = rsqrtf((float)g_degi[i]);
    for (int i = tid; i < NE + NN; i += nthr) {
        if (i < NE) {
            int r = load_idx(ei, 0, i);
            int c = load_idx(ei, 1, i);
            if (r < 0) r = 0; if (r >= NN) r = NN - 1;
            if (c < 0) c = 0; if (c >= NN) c = NN - 1;
            int p = g_off[c] + atomicAdd(&g_cursor[c], 1);
            g_edge[p] = r;
        } else {
            int c = i - NE;
            int p = g_off[c] + atomicAdd(&g_cursor[c], 1);
            g_edge[p] = c;
        }
    }
}

// ---- launch 2: input GEMM; writes hh2 = dinv*relu(xW0+b0), h0, sentinel -----
// GEMM via smem-staged broadcast LDS (no shfl storm on the MIO pipe).
__global__ void __launch_bounds__(256, 4) k_in(const float* __restrict__ x,
                                               const float* __restrict__ W0,
                                               const float* __restrict__ b0) {
    if (blockIdx.x == 0) {
        int t = threadIdx.x;
        if (t < HID) { g_bnS[0][t] = 0.f; g_bnQ[0][t] = 0.f; }
        if (t >= HID && t < HID + 16) g_hh[NN * 16 + (t - HID)] = make_uint2(0, 0);
    }
    __shared__ float2 Ws[INC][32];                   // 32 KB
    __shared__ __align__(16) float4 xstg[8][4][32];  // 16 KB
    for (int idx = threadIdx.x; idx < INC * 32; idx += blockDim.x) {
        int k = idx >> 5, j = idx & 31;
        Ws[k][j] = make_float2(W0[k * HID + 2 * j], W0[k * HID + 2 * j + 1]);
    }
    __syncthreads();
    const u64* __restrict__ Wsu = reinterpret_cast<const u64*>(&Ws[0][0]);
    int lane = threadIdx.x & 31;
    int wid = threadIdx.x >> 5;
    int cg = lane & 15;
    int gw = (blockIdx.x * blockDim.x + threadIdx.x) >> 5;
    int nw = (gridDim.x * blockDim.x) >> 5;
    float2 bv = ((const float2*)b0)[lane];
    for (int base = gw * 4; base < NN; base += nw * 4) {
#pragma unroll
        for (int u = 0; u < 4; u++)
            xstg[wid][u][lane] = ((const float4*)x)[(base + u) * 32 + lane];
        __syncwarp();
        u64 acc[4] = {0, 0, 0, 0};
#pragma unroll 4
        for (int q = 0; q < 32; q++) {   // k = 4q .. 4q+3
            u64 w0 = Wsu[(4 * q + 0) * 32 + lane];
            u64 w1 = Wsu[(4 * q + 1) * 32 + lane];
            u64 w2 = Wsu[(4 * q + 2) * 32 + lane];
            u64 w3 = Wsu[(4 * q + 3) * 32 + lane];
#pragma unroll
            for (int u = 0; u < 4; u++) {
                float4 xq = xstg[wid][u][q];         // broadcast LDS.128
                acc[u] = ffma2(pack2(xq.x, xq.x), w0, acc[u]);
                acc[u] = ffma2(pack2(xq.y, xq.y), w1, acc[u]);
                acc[u] = ffma2(pack2(xq.z, xq.z), w2, acc[u]);
                acc[u] = ffma2(pack2(xq.w, xq.w), w3, acc[u]);
            }
        }
#pragma unroll
        for (int u = 0; u < 4; u++) {
            float ox, oy;
            unpack2(ox, oy, acc[u]);
            ox = fmaxf(ox + bv.x, 0.f);
            oy = fmaxf(oy + bv.y, 0.f);
            float dc = g_dinv[base + u];
            ((__half2*)g_hh)[(base + u) * 32 + lane] =
                __floats2half2_rn(dc * ox, dc * oy);
            float lx0 = __shfl_sync(0xffffffffu, ox, 2 * cg);
            float ly0 = __shfl_sync(0xffffffffu, oy, 2 * cg);
            float lx1 = __shfl_sync(0xffffffffu, ox, 2 * cg + 1);
            float ly1 = __shfl_sync(0xffffffffu, oy, 2 * cg + 1);
            if (lane < 16)
                g_h0[(base + u) * 16 + lane] = make_float4(lx0, ly0, lx1, ly1);
        }
        __syncwarp();
    }
}

// ---- launch 3: ALL 8 layers, persistent, grid-synced ------------------------
// U=8 node batches; bare-index edges; all 9 offsets prefetched per batch.
__global__ void __launch_bounds__(BLK, 3) k_layers(const float* __restrict__ convW,
                                                   const float* __restrict__ gam,
                                                   const float* __restrict__ bet) {
    __shared__ float2 Ws[HID][32];                 // 16 KB
    __shared__ __align__(16) float4 stg[8][8][16]; // 16 KB: per-warp s staging
    __shared__ float2 rS[8][32], rQ[8][32];
    __shared__ float s_scale[HID], s_shift[HID];
    int lane = threadIdx.x & 31;
    int wid = threadIdx.x >> 5;
    int hl = lane >> 4;
    int cg = lane & 15;
    int gw = (blockIdx.x * blockDim.x + threadIdx.x) >> 5;
    int nw = (gridDim.x * blockDim.x) >> 5;
    const uint2* __restrict__ hhp = g_hh;
    const float4* __restrict__ h0p = g_h0;
    float2* __restrict__ s2p = (float2*)g_s2;
    int step = 0;

    for (int l = 0; l < NLAYERS; l++) {
        int par = l & 1;
        float beta_l = logf(0.5f / (float)(l + 1) + 1.0f);
        float ob = 1.0f - beta_l;
        const float* Wc = convW + l * HID * HID;
        for (int idx = threadIdx.x; idx < HID * 32; idx += blockDim.x) {
            int k = idx >> 5, j = idx & 31;
            Ws[k][j] = make_float2(Wc[k * HID + 2 * j], Wc[k * HID + 2 * j + 1]);
        }
        __syncthreads();
        const u64* __restrict__ Wsu = reinterpret_cast<const u64*>(&Ws[0][0]);
        float2 bsum = {0, 0}, bsq = {0, 0};

        for (int base = gw * 8; base < NN; base += nw * 8) {
            // prefetch all 9 offsets: kills the per-node off->meta serial chain
            int4 oa = *(const int4*)&g_off[base];
            int4 ob4 = *(const int4*)&g_off[base + 4];
            int o8 = g_off[base + 8];
            int offv[9] = {oa.x, oa.y, oa.z, oa.w,
                           ob4.x, ob4.y, ob4.z, ob4.w, o8};
            // ---- gather + residual for 8 nodes; stage s rows in smem ----
#pragma unroll
            for (int u = 0; u < 8; u++) {
                int node = base + u;
                int e0 = offv[u], e1 = offv[u + 1];
                float ax = 0.f, ay = 0.f, az = 0.f, aw = 0.f;
#define GATH(i0, i1) { \
    int r_ = hl ? (i1) : (i0); \
    uint2 v_ = __ldg(&hhp[r_ * 16 + cg]); \
    float2 f0_ = __half22float2(*(const __half2*)&v_.x); \
    float2 f1_ = __half22float2(*(const __half2*)&v_.y); \
    ax += f0_.x; ay += f0_.y; az += f1_.x; aw += f1_.y; }
                for (int e = e0; e < e1; e += 8) {
                    const int4* ip = (const int4*)(g_edge + e);
                    int4 a = ip[0], b = ip[1];
                    GATH(a.x, a.y) GATH(a.z, a.w)
                    GATH(b.x, b.y) GATH(b.z, b.w)
                }
#undef GATH
                ax += __shfl_xor_sync(0xffffffffu, ax, 16);
                ay += __shfl_xor_sync(0xffffffffu, ay, 16);
                az += __shfl_xor_sync(0xffffffffu, az, 16);
                aw += __shfl_xor_sync(0xffffffffu, aw, 16);
                float c9 = 0.9f * g_dinv[node];
                float4 h0v = h0p[node * 16 + cg];
                float4 sv;
                sv.x = fmaf(c9, ax, 0.1f * h0v.x);
                sv.y = fmaf(c9, ay, 0.1f * h0v.y);
                sv.z = fmaf(c9, az, 0.1f * h0v.z);
                sv.w = fmaf(c9, aw, 0.1f * h0v.w);
                if (hl == 0) stg[wid][u][cg] = sv;
            }
            __syncwarp();
            // ---- GEMM from smem staging: t[u] (2 ch/lane) = s[u] @ W ----
            u64 t[8] = {0, 0, 0, 0, 0, 0, 0, 0};
#pragma unroll 4
            for (int q = 0; q < 16; q++) {
                u64 w0 = Wsu[(4 * q + 0) * 32 + lane];
                u64 w1 = Wsu[(4 * q + 1) * 32 + lane];
                u64 w2 = Wsu[(4 * q + 2) * 32 + lane];
                u64 w3 = Wsu[(4 * q + 3) * 32 + lane];
#pragma unroll
                for (int u = 0; u < 8; u++) {
                    float4 sq = stg[wid][u][q];      // broadcast LDS.128
                    t[u] = ffma2(pack2(sq.x, sq.x), w0, t[u]);
                    t[u] = ffma2(pack2(sq.y, sq.y), w1, t[u]);
                    t[u] = ffma2(pack2(sq.z, sq.z), w2, t[u]);
                    t[u] = ffma2(pack2(sq.w, sq.w), w3, t[u]);
                }
            }
#pragma unroll
            for (int u = 0; u < 8; u++) {
                int node = base + u;
                float2 sl = *(const float2*)((const float*)&stg[wid][u][0] + 2 * lane);
                float tx, ty;
                unpack2(tx, ty, t[u]);
                float2 o;
                o.x = ob * sl.x + beta_l * tx;
                o.y = ob * sl.y + beta_l * ty;
                s2p[node * 32 + lane] = o;
                bsum.x += o.x; bsum.y += o.y;
                bsq.x = fmaf(o.x, o.x, bsq.x);
                bsq.y = fmaf(o.y, o.y, bsq.y);
            }
            __syncwarp();
        }

        __syncthreads();
        rS[wid][lane] = bsum; rQ[wid][lane] = bsq;
        __syncthreads();
        if (threadIdx.x < 32) {
            float2 S = rS[0][threadIdx.x], Q = rQ[0][threadIdx.x];
#pragma unroll
            for (int j = 1; j < 8; j++) {
                S.x += rS[j][threadIdx.x].x; S.y += rS[j][threadIdx.x].y;
                Q.x += rQ[j][threadIdx.x].x; Q.y += rQ[j][threadIdx.x].y;
            }
            atomicAdd(&g_bnS[par][2 * threadIdx.x],     S.x);
            atomicAdd(&g_bnS[par][2 * threadIdx.x + 1], S.y);
            atomicAdd(&g_bnQ[par][2 * threadIdx.x],     Q.x);
            atomicAdd(&g_bnQ[par][2 * threadIdx.x + 1], Q.y);
        }
        gsync(&g_lctr, (++step) * GRID_L);

        if (threadIdx.x < HID) {
            float inv = 1.0f / (float)NN;
            float mu = g_bnS[par][threadIdx.x] * inv;
            float var = g_bnQ[par][threadIdx.x] * inv - mu * mu;
            float rs = rsqrtf(var + 1e-5f);
            float sc = rs * gam[l * HID + threadIdx.x];
            s_scale[threadIdx.x] = sc;
            s_shift[threadIdx.x] = bet[l * HID + threadIdx.x] - mu * sc;
        } else if (threadIdx.x < 2 * HID) {
            g_bnS[par ^ 1][threadIdx.x - HID] = 0.f;
            g_bnQ[par ^ 1][threadIdx.x - HID] = 0.f;
        }
        __syncthreads();
        int writeF32 = (l == NLAYERS - 1);
        for (int i = blockIdx.x * blockDim.x + threadIdx.x; i < NN * 16;
             i += gridDim.x * blockDim.x) {
            float4 v = ((const float4*)g_s2)[i];
            int c = (i & 15) << 2;
            v.x = fmaxf(fmaf(v.x, s_scale[c],     s_shift[c]),     0.f);
            v.y = fmaxf(fmaf(v.y, s_scale[c + 1], s_shift[c + 1]), 0.f);
            v.z = fmaxf(fmaf(v.z, s_scale[c + 2], s_shift[c + 2]), 0.f);
            v.w = fmaxf(fmaf(v.w, s_scale[c + 3], s_shift[c + 3]), 0.f);
            float dc = g_dinv[i >> 4];
            __half2 p0 = __floats2half2_rn(dc * v.x, dc * v.y);
            __half2 p1 = __floats2half2_rn(dc * v.z, dc * v.w);
            uint2 pk;
            pk.x = *reinterpret_cast<unsigned int*>(&p0);
            pk.y = *reinterpret_cast<unsigned int*>(&p1);
            g_hh[i] = pk;
            if (writeF32) ((float4*)g_h)[i] = v;
        }
        gsync(&g_lctr, (++step) * GRID_L);
    }
}

// ---- launch 4: output GEMM out = h @ Wout + bout (smem-staged) --------------
__global__ void __launch_bounds__(256, 4) k_out(const float* __restrict__ Wout,
                                                const float* __restrict__ bout,
                                                float* __restrict__ out) {
    __shared__ float2 Wo[HID][32];                   // 16 KB
    __shared__ __align__(16) float2 hstg[8][4][32];  // 8 KB
    for (int idx = threadIdx.x; idx < HID * 32; idx += blockDim.x) {
        int k = idx >> 5, j = idx & 31;
        float w0 = Wout[k * OUTC + j];
        float w1 = (j < 8) ? Wout[k * OUTC + 32 + j] : 0.f;
        Wo[k][j] = make_float2(w0, w1);
    }
    __syncthreads();
    const u64* __restrict__ Wou = reinterpret_cast<const u64*>(&Wo[0][0]);
    int lane = threadIdx.x & 31;
    int wid = threadIdx.x >> 5;
    int gw = (blockIdx.x * blockDim.x + threadIdx.x) >> 5;
    int nw = (gridDim.x * blockDim.x) >> 5;
    const float2* __restrict__ hp = (const float2*)g_h;
    float b0v = bout[lane];
    float b1v = (lane < 8) ? bout[32 + lane] : 0.f;
    for (int base = gw * 4; base < NN; base += nw * 4) {
#pragma unroll
        for (int u = 0; u < 4; u++)
            hstg[wid][u][lane] = hp[(base + u) * 32 + lane];
        __syncwarp();
        u64 acc[4] = {0, 0, 0, 0};
#pragma unroll 4
        for (int q = 0; q < 16; q++) {   // k = 4q .. 4q+3
            u64 w0 = Wou[(4 * q + 0) * 32 + lane];
            u64 w1 = Wou[(4 * q + 1) * 32 + lane];
            u64 w2 = Wou[(4 * q + 2) * 32 + lane];
            u64 w3 = Wou[(4 * q + 3) * 32 + lane];
#pragma unroll
            for (int u = 0; u < 4; u++) {
                float4 hq = *(const float4*)&hstg[wid][u][2 * q];  // broadcast LDS.128
                acc[u] = ffma2(pack2(hq.x, hq.x), w0, acc[u]);
                acc[u] = ffma2(pack2(hq.y, hq.y), w1, acc[u]);
                acc[u] = ffma2(pack2(hq.z, hq.z), w2, acc[u]);
                acc[u] = ffma2(pack2(hq.w, hq.w), w3, acc[u]);
            }
        }
#pragma unroll
        for (int u = 0; u < 4; u++) {
            int node = base + u;
            float a0, a1;
            unpack2(a0, a1, acc[u]);
            out[node * OUTC + lane] = a0 + b0v;
            if (lane < 8) out[node * OUTC + 32 + lane] = a1 + b1v;
        }
        __syncwarp();
    }
}

// ---- launcher ---------------------------------------------------------------
extern "C" void kernel_launch(void* const* d_in, const int* in_sizes, int n_in,
                              void* d_out, int out_size) {
    const float* x     = (const float*)d_in[0];
    const void*  ei    = d_in[1];
    const float* W0    = (const float*)d_in[2];
    const float* b0    = (const float*)d_in[3];
    const float* convW = (const float*)d_in[4];
    const float* gam   = (const float*)d_in[5];
    const float* bet   = (const float*)d_in[6];
    const float* Wout  = (const float*)d_in[7];
    const float* bout  = (const float*)d_in[8];
    float* out = (float*)d_out;

    k_init<<<1, 64>>>();                        // 0
    k_prep<<<GRID_P, 256>>>(ei);                // 1
    k_in<<<GRID_E, 256>>>(x, W0, b0);           // 2
    k_layers<<<GRID_L, BLK>>>(convW, gam, bet); // 3  <- profiled slot
    k_out<<<GRID_E, 256>>>(Wout, bout, out);    // 4
}